// round 1
// baseline (speedup 1.0000x reference)
#include <cuda_runtime.h>
#include <math.h>

#define BB 4
#define CC 64
#define NN 6400   // 80*80

// Scratch (module-static device memory; no runtime allocation).
// g_Q : [b][n][c]  query rows, row n = h*80+w holds q[:, w, h] (transposed pixel)
// g_K : [b][c][m]  keys, channel-major, natural pixel order (q[:, m/80, m%80])
// g_V : [b][m][c]  values, row m holds v[:, m%80, m/80] (transposed pixel)
// g_Kc: [b][m][c]  k natural pixel-major (for channel attention)
__device__ float g_Q [BB * NN * CC];
__device__ float g_K [BB * CC * NN];
__device__ float g_V [BB * NN * CC];
__device__ float g_Kc[BB * NN * CC];
__device__ float g_Lp[BB * 32 * CC * CC];   // channel-logit partials
__device__ float g_ma[BB * CC * CC];        // softmaxed channel attention

// ---------------------------------------------------------------------------
// Kernel 1: 1x1 conv qkv. grid (100 pixel-tiles, 2 halves of 96 outputs, 4 b)
// ---------------------------------------------------------------------------
__global__ __launch_bounds__(256) void qkv_kernel(
    const float* __restrict__ x, const float* __restrict__ w,
    const float* __restrict__ bias)
{
    __shared__ float ws[64][100];  // [c][o_local], padded for transpose stores
    __shared__ float xs[64][64];   // [c][p]

    const int b     = blockIdx.z;
    const int half  = blockIdx.y;
    const int n0    = blockIdx.x * 64;
    const int tid   = threadIdx.x;
    const int obase = half * 96;

    // load w transposed: ws[c][o] = w[obase+o][c]
    for (int idx = tid; idx < 96 * 64; idx += 256) {
        int c = idx >> 6;        // within a 64-chunk lanes walk c? -> we want coalesced read:
        int o = idx & 63;        // not used this way; see below
        (void)c; (void)o;
        break;
    }
    // coalesced read (consecutive lanes -> consecutive c), store stride-100 (4-way ok)
    for (int idx = tid; idx < 96 * 64; idx += 256) {
        int o = idx >> 6;
        int c = idx & 63;
        ws[c][o] = w[(size_t)(obase + o) * 64 + c];
    }
    // load x tile: xs[c][p] = x[b][c][n0+p]
    for (int idx = tid; idx < 64 * 64; idx += 256) {
        int c = idx >> 6;
        int p = idx & 63;
        xs[c][p] = x[((size_t)b * 64 + c) * NN + n0 + p];
    }
    __syncthreads();

    const int p  = tid & 63;         // pixel within tile
    const int o0 = (tid >> 6) * 24;  // 24 local outputs

    float acc[24];
#pragma unroll
    for (int j = 0; j < 24; j++) acc[j] = 0.f;

#pragma unroll 4
    for (int c = 0; c < 64; c++) {
        float xv = xs[c][p];
#pragma unroll
        for (int j4 = 0; j4 < 24; j4 += 4) {
            float4 wv = *(const float4*)&ws[c][o0 + j4];
            acc[j4 + 0] += xv * wv.x;
            acc[j4 + 1] += xv * wv.y;
            acc[j4 + 2] += xv * wv.z;
            acc[j4 + 3] += xv * wv.w;
        }
    }

    const int n  = n0 + p;
    const int h  = n / 80;
    const int wq = n % 80;
    const int nt = wq * 80 + h;   // transposed pixel index

#pragma unroll
    for (int j4 = 0; j4 < 24; j4 += 4) {
        const int o = obase + o0 + j4;  // global output channel (multiple of 4)
        float4 v4;
        v4.x = acc[j4 + 0] + bias[o + 0];
        v4.y = acc[j4 + 1] + bias[o + 1];
        v4.z = acc[j4 + 2] + bias[o + 2];
        v4.w = acc[j4 + 3] + bias[o + 3];
        if (o < 64) {
            // q: keys channel-major (coalesced across lanes), queries row-major at nt
            g_K[((size_t)b * 64 + o + 0) * NN + n] = v4.x;
            g_K[((size_t)b * 64 + o + 1) * NN + n] = v4.y;
            g_K[((size_t)b * 64 + o + 2) * NN + n] = v4.z;
            g_K[((size_t)b * 64 + o + 3) * NN + n] = v4.w;
            *(float4*)&g_Q[((size_t)b * NN + nt) * 64 + o] = v4;
        } else if (o < 128) {
            *(float4*)&g_Kc[((size_t)b * NN + n) * 64 + (o - 64)] = v4;
        } else {
            *(float4*)&g_V[((size_t)b * NN + nt) * 64 + (o - 128)] = v4;
        }
    }
}

// ---------------------------------------------------------------------------
// Kernel 2a: channel-attn logit partials. grid (32 chunks, 4 b), 256 thr
// L[c][c'] = sum_m Kc[m][c] * Q[m][c']
// ---------------------------------------------------------------------------
__global__ __launch_bounds__(256) void chan_logits_kernel()
{
    const int b = blockIdx.y, chunk = blockIdx.x;
    const int tid = threadIdx.x;
    const int tx = tid & 15, ty = tid >> 4;
    const float* __restrict__ Kc = g_Kc + (size_t)b * NN * CC;
    const float* __restrict__ Qm = g_Q  + (size_t)b * NN * CC;

    float acc[4][4];
#pragma unroll
    for (int i = 0; i < 4; i++)
#pragma unroll
        for (int j = 0; j < 4; j++) acc[i][j] = 0.f;

    const int m0 = chunk * 200;
#pragma unroll 2
    for (int m = m0; m < m0 + 200; m++) {
        float4 kv4 = *(const float4*)(Kc + (size_t)m * 64 + ty * 4);
        float4 qv4 = *(const float4*)(Qm + (size_t)m * 64 + tx * 4);
        float kv[4] = {kv4.x, kv4.y, kv4.z, kv4.w};
        float qv[4] = {qv4.x, qv4.y, qv4.z, qv4.w};
#pragma unroll
        for (int i = 0; i < 4; i++)
#pragma unroll
            for (int j = 0; j < 4; j++)
                acc[i][j] += kv[i] * qv[j];
    }

    float* Lp = g_Lp + ((size_t)b * 32 + chunk) * 64 * 64;
#pragma unroll
    for (int i = 0; i < 4; i++) {
        float4 o4 = make_float4(acc[i][0], acc[i][1], acc[i][2], acc[i][3]);
        *(float4*)(Lp + (size_t)(ty * 4 + i) * 64 + tx * 4) = o4;
    }
}

// ---------------------------------------------------------------------------
// Kernel 2b: reduce partials + row softmax. grid 4, 64 threads (thread=row c)
// ---------------------------------------------------------------------------
__global__ void chan_softmax_kernel()
{
    const int b = blockIdx.x;
    const int c = threadIdx.x;
    float s[64];
#pragma unroll
    for (int j = 0; j < 64; j++) s[j] = 0.f;

    for (int ch = 0; ch < 32; ch++) {
        const float* p = g_Lp + (((size_t)b * 32 + ch) * 64 + c) * 64;
#pragma unroll
        for (int j4 = 0; j4 < 64; j4 += 4) {
            float4 v = *(const float4*)(p + j4);
            s[j4 + 0] += v.x; s[j4 + 1] += v.y;
            s[j4 + 2] += v.z; s[j4 + 3] += v.w;
        }
    }
    float mx = -INFINITY;
#pragma unroll
    for (int j = 0; j < 64; j++) mx = fmaxf(mx, s[j]);
    float sum = 0.f;
#pragma unroll
    for (int j = 0; j < 64; j++) { s[j] = expf(s[j] - mx); sum += s[j]; }
    const float inv = 1.f / sum;
    float* o = g_ma + ((size_t)b * 64 + c) * 64;
#pragma unroll
    for (int j4 = 0; j4 < 64; j4 += 4) {
        float4 v = make_float4(s[j4] * inv, s[j4 + 1] * inv,
                               s[j4 + 2] * inv, s[j4 + 3] * inv);
        *(float4*)(o + j4) = v;
    }
}

// ---------------------------------------------------------------------------
// Kernel 3: channel apply (writes output base). grid (100, 4), 256 thr
// out[b][c][n] = sum_c' ma[c][c'] * v_nat[c'][n];  v_nat[c'][n] = g_V[b][nt][c']
// ---------------------------------------------------------------------------
__global__ __launch_bounds__(256) void chan_apply_kernel(float* __restrict__ out)
{
    __shared__ float vs[64][64];   // [c'][p]
    __shared__ float mas[64][65];  // [c'][c], padded (scalar reads, no conflict)

    const int b  = blockIdx.y;
    const int n0 = blockIdx.x * 64;
    const int tid = threadIdx.x;
    const int tx = tid & 15, ty = tid >> 4;

    // mas[cp][c] = g_ma[b][c][cp]  (coalesced read, conflict-free padded store)
    for (int idx = tid; idx < 4096; idx += 256) {
        int c  = idx >> 6;
        int cp = idx & 63;
        mas[cp][c] = g_ma[((size_t)b * 64 + c) * 64 + cp];
    }
    // vs[cp][p] = g_V[b][nt(p)][cp]
    {
        int p  = tid >> 2;
        int cb = (tid & 3) * 16;
        int n  = n0 + p;
        int nt = (n % 80) * 80 + n / 80;
        const float* vp = g_V + ((size_t)b * NN + nt) * 64 + cb;
#pragma unroll
        for (int k = 0; k < 4; k++) {
            float4 v4 = *(const float4*)(vp + 4 * k);
            vs[cb + 4 * k + 0][p] = v4.x;
            vs[cb + 4 * k + 1][p] = v4.y;
            vs[cb + 4 * k + 2][p] = v4.z;
            vs[cb + 4 * k + 3][p] = v4.w;
        }
    }
    __syncthreads();

    float acc[4][4];
#pragma unroll
    for (int i = 0; i < 4; i++)
#pragma unroll
        for (int j = 0; j < 4; j++) acc[i][j] = 0.f;

#pragma unroll 4
    for (int cp = 0; cp < 64; cp++) {
        float mv[4];
#pragma unroll
        for (int i = 0; i < 4; i++) mv[i] = mas[cp][ty * 4 + i];
        float4 v4 = *(const float4*)&vs[cp][tx * 4];
        float vv[4] = {v4.x, v4.y, v4.z, v4.w};
#pragma unroll
        for (int i = 0; i < 4; i++)
#pragma unroll
            for (int j = 0; j < 4; j++)
                acc[i][j] += mv[i] * vv[j];
    }
#pragma unroll
    for (int i = 0; i < 4; i++) {
        float4 o4 = make_float4(acc[i][0], acc[i][1], acc[i][2], acc[i][3]);
        *(float4*)(out + ((size_t)b * 64 + ty * 4 + i) * NN + n0 + tx * 4) = o4;
    }
}

// ---------------------------------------------------------------------------
// Kernel 4: spatial flash attention (adds into out). grid (100, 4), 256 thr
// out[b][c][n] += sum_m softmax_m(Q[n].K[:,m]) * V[m][c]
// smem: Qs[64][64] (c-major), KP[64][68] (K tile c-major, reused as P r-major),
//       Vs[64][64] (m-major)
// ---------------------------------------------------------------------------
__global__ __launch_bounds__(256) void flash_kernel(float* __restrict__ out)
{
    extern __shared__ float sm[];
    float* Qs = sm;                   // 64*64
    float* KP = sm + 4096;            // 64*68
    float* Vs = sm + 4096 + 64 * 68;  // 64*64

    const int b  = blockIdx.y;
    const int n0 = blockIdx.x * 64;
    const int tid = threadIdx.x;
    const int tx = tid & 15, ty = tid >> 4;

    const float* __restrict__ Q = g_Q + (size_t)b * NN * CC;
    const float* __restrict__ K = g_K + (size_t)b * CC * NN;
    const float* __restrict__ V = g_V + (size_t)b * NN * CC;

    const int rr = tid >> 2;          // 0..63
    const int cb = (tid & 3) * 16;

    // Q tile transpose: Qs[c][r] = Q[(n0+r)][c]
    {
        const float* qp = Q + ((size_t)(n0 + rr)) * 64 + cb;
#pragma unroll
        for (int k = 0; k < 4; k++) {
            float4 q4 = *(const float4*)(qp + 4 * k);
            Qs[(cb + 4 * k + 0) * 64 + rr] = q4.x;
            Qs[(cb + 4 * k + 1) * 64 + rr] = q4.y;
            Qs[(cb + 4 * k + 2) * 64 + rr] = q4.z;
            Qs[(cb + 4 * k + 3) * 64 + rr] = q4.w;
        }
    }

    float O[4][4];
    float mrow[4], lrow[4];
#pragma unroll
    for (int i = 0; i < 4; i++) {
        mrow[i] = -INFINITY; lrow[i] = 0.f;
#pragma unroll
        for (int j = 0; j < 4; j++) O[i][j] = 0.f;
    }

    for (int mt = 0; mt < 100; mt++) {
        const int m0 = mt * 64;
        __syncthreads();   // previous-iter readers of KP/Vs done
        {
            // K tile: KP[c][m] (row len 68), source channel-major -> coalesced
            const float* kp = K + (size_t)rr * NN + m0 + cb;
            float* kdst = KP + rr * 68 + cb;
#pragma unroll
            for (int k = 0; k < 4; k++)
                *(float4*)(kdst + 4 * k) = *(const float4*)(kp + 4 * k);
            // V tile: Vs[m][c]
            const float* vp = V + ((size_t)(m0 + rr)) * 64 + cb;
            float* vdst = Vs + rr * 64 + cb;
#pragma unroll
            for (int k = 0; k < 4; k++)
                *(float4*)(vdst + 4 * k) = *(const float4*)(vp + 4 * k);
        }
        __syncthreads();

        // S = Q @ K^T  (rows r=ty*4+i, cols m=tx*4+j)
        float S[4][4];
#pragma unroll
        for (int i = 0; i < 4; i++)
#pragma unroll
            for (int j = 0; j < 4; j++) S[i][j] = 0.f;

#pragma unroll 8
        for (int c = 0; c < 64; c++) {
            float4 q4 = *(const float4*)(Qs + c * 64 + ty * 4);
            float4 k4 = *(const float4*)(KP + c * 68 + tx * 4);
            float qa[4] = {q4.x, q4.y, q4.z, q4.w};
            float ka[4] = {k4.x, k4.y, k4.z, k4.w};
#pragma unroll
            for (int i = 0; i < 4; i++)
#pragma unroll
                for (int j = 0; j < 4; j++)
                    S[i][j] += qa[i] * ka[j];
        }

        // online softmax update (row groups = 16 lanes sharing ty)
#pragma unroll
        for (int i = 0; i < 4; i++) {
            float m = fmaxf(fmaxf(S[i][0], S[i][1]), fmaxf(S[i][2], S[i][3]));
#pragma unroll
            for (int sft = 8; sft >= 1; sft >>= 1)
                m = fmaxf(m, __shfl_xor_sync(0xffffffffu, m, sft));
            float mnew  = fmaxf(mrow[i], m);
            float scale = __expf(mrow[i] - mnew);
            mrow[i] = mnew;
            float ts = 0.f;
#pragma unroll
            for (int j = 0; j < 4; j++) {
                S[i][j] = __expf(S[i][j] - mnew);
                ts += S[i][j];
            }
#pragma unroll
            for (int sft = 8; sft >= 1; sft >>= 1)
                ts += __shfl_xor_sync(0xffffffffu, ts, sft);
            lrow[i] = lrow[i] * scale + ts;
#pragma unroll
            for (int j = 0; j < 4; j++) O[i][j] *= scale;
        }

        __syncthreads();   // all S-phase reads of KP done before overwrite
        // store P into KP as [r][m] (row len 68 -> conflict-free)
#pragma unroll
        for (int i = 0; i < 4; i++) {
            float4 p4 = make_float4(S[i][0], S[i][1], S[i][2], S[i][3]);
            *(float4*)(KP + (ty * 4 + i) * 68 + tx * 4) = p4;
        }
        __syncthreads();

        // O += P @ V
#pragma unroll 4
        for (int mb = 0; mb < 16; mb++) {
            float4 p0 = *(const float4*)(KP + (ty * 4 + 0) * 68 + mb * 4);
            float4 p1 = *(const float4*)(KP + (ty * 4 + 1) * 68 + mb * 4);
            float4 p2 = *(const float4*)(KP + (ty * 4 + 2) * 68 + mb * 4);
            float4 p3 = *(const float4*)(KP + (ty * 4 + 3) * 68 + mb * 4);
            float pa[4][4] = {{p0.x, p0.y, p0.z, p0.w},
                              {p1.x, p1.y, p1.z, p1.w},
                              {p2.x, p2.y, p2.z, p2.w},
                              {p3.x, p3.y, p3.z, p3.w}};
#pragma unroll
            for (int k = 0; k < 4; k++) {
                float4 v4 = *(const float4*)(Vs + (mb * 4 + k) * 64 + tx * 4);
                float va[4] = {v4.x, v4.y, v4.z, v4.w};
#pragma unroll
                for (int i = 0; i < 4; i++)
#pragma unroll
                    for (int j = 0; j < 4; j++)
                        O[i][j] += pa[i][k] * va[j];
            }
        }
    }

    // epilogue: normalize and accumulate into out
    float inv[4];
#pragma unroll
    for (int i = 0; i < 4; i++) inv[i] = 1.f / lrow[i];
#pragma unroll
    for (int j = 0; j < 4; j++) {
        const int c = tx * 4 + j;
        float* op = out + ((size_t)b * 64 + c) * NN + n0 + ty * 4;
        float4 o4 = *(float4*)op;
        o4.x += O[0][j] * inv[0];
        o4.y += O[1][j] * inv[1];
        o4.z += O[2][j] * inv[2];
        o4.w += O[3][j] * inv[3];
        *(float4*)op = o4;
    }
}

// ---------------------------------------------------------------------------
extern "C" void kernel_launch(void* const* d_in, const int* in_sizes, int n_in,
                              void* d_out, int out_size)
{
    const float* x    = (const float*)d_in[0];
    const float* w    = (const float*)d_in[1];
    const float* bias = (const float*)d_in[2];
    float* out = (float*)d_out;

    const int flash_smem = (4096 + 64 * 68 + 4096) * 4;  // 50176 B
    cudaFuncSetAttribute(flash_kernel,
                         cudaFuncAttributeMaxDynamicSharedMemorySize, flash_smem);

    qkv_kernel<<<dim3(100, 2, 4), 256>>>(x, w, bias);
    chan_logits_kernel<<<dim3(32, 4), 256>>>();
    chan_softmax_kernel<<<4, 64>>>();
    chan_apply_kernel<<<dim3(100, 4), 256>>>(out);
    flash_kernel<<<dim3(100, 4), 256, flash_smem>>>(out);
}